// round 1
// baseline (speedup 1.0000x reference)
#include <cuda_runtime.h>

// ---------------------------------------------------------------------------
// Problem constants (fixed shapes for this dataset)
//   T = S = 512, B = 64, D = 512, H = 5, QHD = 32, PHD = 4, PD = 192
//   lm proj: (T*B, 512) @ (512, 180) -> cols [0,160)=q (h*32+d), [160,180)=p (h*4+d)
//   am proj: (S*B, 512) @ (512, 160) -> k (h*32+d)
//   pe: (1023, 192) @ (192, 20) -> (1023, h*4+d)
//   out[h][b][t][j] = softmax_j( q.k + p.pe[j - t + 511] + mask )
// ---------------------------------------------------------------------------

static __device__ float g_lm[32768 * 180];   // projected lm (q | p), row-major
static __device__ float g_k [32768 * 160];   // projected am (k), row-major
static __device__ float g_pe[1023 * 20];     // projected pos emb

// ---------------------------------------------------------------------------
// Projection GEMM: C[M=32768, N] = X[32768, 512] @ W[512, N] + bias
// BM=128, BN=64, BK=16, 256 threads, 8x4 per-thread tile.
// ---------------------------------------------------------------------------
__global__ __launch_bounds__(256)
void proj_gemm_kernel(const float* __restrict__ X, const float* __restrict__ W,
                      const float* __restrict__ bias, float* __restrict__ C,
                      const int N)
{
    __shared__ float Xs[16][128];   // [k][m]
    __shared__ float Ws[16][64];    // [k][n]
    const int tid = threadIdx.x;
    const int m0 = blockIdx.x * 128;
    const int n0 = blockIdx.y * 64;
    const int ty = tid >> 4;        // 0..15 -> rows ty*8..+7
    const int tx = tid & 15;        // 0..15 -> cols tx*4..+3

    float acc[8][4];
#pragma unroll
    for (int i = 0; i < 8; ++i)
#pragma unroll
        for (int j = 0; j < 4; ++j) acc[i][j] = 0.f;

    for (int kt = 0; kt < 512; kt += 16) {
        // load X tile (128 rows x 16 k), transposed into Xs[k][m]
#pragma unroll
        for (int s = 0; s < 2; ++s) {
            const int f4i = tid * 2 + s;            // 0..511
            const int row = f4i >> 2;
            const int c4  = (f4i & 3) << 2;
            const float4 v = *(const float4*)&X[(size_t)(m0 + row) * 512 + kt + c4];
            Xs[c4 + 0][row] = v.x;
            Xs[c4 + 1][row] = v.y;
            Xs[c4 + 2][row] = v.z;
            Xs[c4 + 3][row] = v.w;
        }
        // load W tile (16 k x 64 n), predicated on n < N
#pragma unroll
        for (int s = 0; s < 4; ++s) {
            const int idx = tid + 256 * s;
            const int kr = idx >> 6;
            const int nc = idx & 63;
            const int col = n0 + nc;
            Ws[kr][nc] = (col < N) ? W[(size_t)(kt + kr) * N + col] : 0.f;
        }
        __syncthreads();
#pragma unroll
        for (int kk = 0; kk < 16; ++kk) {
            const float4 a0 = *(const float4*)&Xs[kk][ty * 8];
            const float4 a1 = *(const float4*)&Xs[kk][ty * 8 + 4];
            const float4 b0 = *(const float4*)&Ws[kk][tx * 4];
            const float a[8]  = {a0.x, a0.y, a0.z, a0.w, a1.x, a1.y, a1.z, a1.w};
            const float bv[4] = {b0.x, b0.y, b0.z, b0.w};
#pragma unroll
            for (int i = 0; i < 8; ++i)
#pragma unroll
                for (int j = 0; j < 4; ++j)
                    acc[i][j] = fmaf(a[i], bv[j], acc[i][j]);
        }
        __syncthreads();
    }

    const int col = n0 + tx * 4;
    if (col < N) {                       // N % 4 == 0, so col<N implies col+3<N
        const float4 bb = *(const float4*)&bias[col];
#pragma unroll
        for (int i = 0; i < 8; ++i) {
            const int row = m0 + ty * 8 + i;
            float4 o;
            o.x = acc[i][0] + bb.x;
            o.y = acc[i][1] + bb.y;
            o.z = acc[i][2] + bb.z;
            o.w = acc[i][3] + bb.w;
            *(float4*)&C[(size_t)row * N + col] = o;
        }
    }
}

// ---------------------------------------------------------------------------
// Positional embedding projection: (1023,192) @ (192,20) -> (1023,20). Tiny.
// ---------------------------------------------------------------------------
__global__ __launch_bounds__(256)
void pe_proj_kernel(const float* __restrict__ pos, const float* __restrict__ Wp,
                    float* __restrict__ outp)
{
    const int idx = blockIdx.x * 256 + threadIdx.x;
    if (idx >= 1023 * 20) return;
    const int n = idx / 20;
    const int c = idx % 20;
    float s = 0.f;
#pragma unroll 8
    for (int d = 0; d < 192; ++d)
        s = fmaf(pos[n * 192 + d], Wp[d * 20 + c], s);
    outp[idx] = s;
}

// ---------------------------------------------------------------------------
// Fused attention-weights kernel.
// Block = (t-tile of 32 rows, b, h). 256 threads = 8 warps.
// Warp ty handles rows ty*4..ty*4+3; lane tx covers cols cp*128 + tx*4 (cp=0..3).
// Scores kept entirely in registers (acc[4][16]); single pass, one write.
// ---------------------------------------------------------------------------
__global__ __launch_bounds__(256, 2)
void attn_kernel(const float* __restrict__ lmP, const float* __restrict__ kP,
                 const float* __restrict__ peP, const unsigned char* __restrict__ mask,
                 float* __restrict__ out)
{
    extern __shared__ float smem[];
    float* ks = smem;                               // [32][512]  (d-major, unpadded for LDS.128)
    float* qs = ks + 32 * 512;                      // [32][32]   (d-major)
    float4* pes = (float4*)(qs + 32 * 32);          // [544] pe slice (4 floats each)
    float4* ps  = pes + 544;                        // [32] p per local row
    unsigned char* msk = (unsigned char*)(ps + 32); // [512]

    const int t0 = blockIdx.x * 32;
    const int b  = blockIdx.y;
    const int h  = blockIdx.z;
    const int tid = threadIdx.x;

    // ---- K tile: transpose 512x32 -> ks[d][j]; lanes write consecutive j (conflict-free)
#pragma unroll
    for (int s = 0; s < 16; ++s) {
        const int it = tid + 256 * s;               // 0..4095
        const int d4 = it >> 9;                     // 0..7
        const int j  = it & 511;
        const float4 v = *(const float4*)&kP[((size_t)j * 64 + b) * 160 + h * 32 + d4 * 4];
        ks[(d4 * 4 + 0) * 512 + j] = v.x;
        ks[(d4 * 4 + 1) * 512 + j] = v.y;
        ks[(d4 * 4 + 2) * 512 + j] = v.z;
        ks[(d4 * 4 + 3) * 512 + j] = v.w;
    }
    // ---- Q tile: 32x32 -> qs[d][r]
    {
        const int d4 = tid >> 5;                    // 0..7
        const int r  = tid & 31;
        const float4 v = *(const float4*)&lmP[((size_t)(t0 + r) * 64 + b) * 180 + h * 32 + d4 * 4];
        qs[(d4 * 4 + 0) * 32 + r] = v.x;
        qs[(d4 * 4 + 1) * 32 + r] = v.y;
        qs[(d4 * 4 + 2) * 32 + r] = v.z;
        qs[(d4 * 4 + 3) * 32 + r] = v.w;
    }
    // ---- p rows, pe slice, mask row
    if (tid < 32)
        ps[tid] = *(const float4*)&lmP[((size_t)(t0 + tid) * 64 + b) * 180 + 160 + h * 4];
    for (int it = tid; it < 543; it += 256) {
        const int n = 480 - t0 + it;                // global pe index, always in [0,1023)
        pes[it] = *(const float4*)&peP[n * 20 + h * 4];
    }
    for (int it = tid; it < 512; it += 256) msk[it] = mask[b * 512 + it];
    __syncthreads();

    const int ty = tid >> 5;                        // warp -> row group
    const int tx = tid & 31;                        // lane -> col group

    const float4* ks4 = (const float4*)ks;          // [32][128]
    const float4* qs4 = (const float4*)qs;          // [32][8]

    float acc[4][16];
#pragma unroll
    for (int i = 0; i < 4; ++i)
#pragma unroll
        for (int j = 0; j < 16; ++j) acc[i][j] = 0.f;

    // ---- content scores: q (broadcast LDS.128) x k (conflict-free LDS.128), 16 FMA per d
#pragma unroll
    for (int cp = 0; cp < 4; ++cp) {
#pragma unroll 8
        for (int d = 0; d < 32; ++d) {
            const float4 kv = ks4[d * 128 + cp * 32 + tx];
            const float4 qv = qs4[d * 8 + ty];
            const float qa[4] = {qv.x, qv.y, qv.z, qv.w};
            const float ka[4] = {kv.x, kv.y, kv.z, kv.w};
#pragma unroll
            for (int i = 0; i < 4; ++i)
#pragma unroll
                for (int c = 0; c < 4; ++c)
                    acc[i][cp * 4 + c] = fmaf(qa[i], ka[c], acc[i][cp * 4 + c]);
        }
    }

    // ---- positional scores: rel-shift index n_local = j + 31 - r_local (t0 cancels)
#pragma unroll
    for (int i = 0; i < 4; ++i) {
        const int rl = ty * 4 + i;
        const float4 pv = ps[rl];
#pragma unroll
        for (int cp = 0; cp < 4; ++cp)
#pragma unroll
            for (int c = 0; c < 4; ++c) {
                const int nl = cp * 128 + tx * 4 + c + 31 - rl;   // in [0, 542]
                const float4 ev = pes[nl];
                acc[i][cp * 4 + c] += pv.x * ev.x + pv.y * ev.y + pv.z * ev.z + pv.w * ev.w;
            }
    }

    // ---- mask + per-row softmax (warp handles a row with all 32 lanes) + write once
#pragma unroll
    for (int i = 0; i < 4; ++i) {
#pragma unroll
        for (int cp = 0; cp < 4; ++cp)
#pragma unroll
            for (int c = 0; c < 4; ++c) {
                const int j = cp * 128 + tx * 4 + c;
                if (msk[j]) acc[i][cp * 4 + c] = -1000.f;
            }
        float m = -3.4e38f;
#pragma unroll
        for (int j = 0; j < 16; ++j) m = fmaxf(m, acc[i][j]);
#pragma unroll
        for (int off = 16; off > 0; off >>= 1)
            m = fmaxf(m, __shfl_xor_sync(0xffffffffu, m, off));
        float sum = 0.f;
#pragma unroll
        for (int j = 0; j < 16; ++j) {
            acc[i][j] = __expf(acc[i][j] - m);
            sum += acc[i][j];
        }
#pragma unroll
        for (int off = 16; off > 0; off >>= 1)
            sum += __shfl_xor_sync(0xffffffffu, sum, off);
        const float inv = 1.f / sum;
        const int rg = t0 + ty * 4 + i;
        const size_t base = (((size_t)h * 64 + b) * 512 + rg) * 512;
#pragma unroll
        for (int cp = 0; cp < 4; ++cp) {
            float4 o;
            o.x = acc[i][cp * 4 + 0] * inv;
            o.y = acc[i][cp * 4 + 1] * inv;
            o.z = acc[i][cp * 4 + 2] * inv;
            o.w = acc[i][cp * 4 + 3] * inv;
            *(float4*)&out[base + cp * 128 + tx * 4] = o;
        }
    }
}

// ---------------------------------------------------------------------------
// Launch
// ---------------------------------------------------------------------------
extern "C" void kernel_launch(void* const* d_in, const int* in_sizes, int n_in,
                              void* d_out, int out_size)
{
    const float* lm_pruned = (const float*)d_in[0];
    const float* am_pruned = (const float*)d_in[1];
    const float* pos_emb   = (const float*)d_in[2];
    const unsigned char* kpm = (const unsigned char*)d_in[3];
    const float* W_lm  = (const float*)d_in[4];
    const float* b_lm  = (const float*)d_in[5];
    const float* W_am  = (const float*)d_in[6];
    const float* b_am  = (const float*)d_in[7];
    const float* W_pos = (const float*)d_in[8];
    float* out = (float*)d_out;

    float *p_lm, *p_k, *p_pe;
    cudaGetSymbolAddress((void**)&p_lm, g_lm);
    cudaGetSymbolAddress((void**)&p_k,  g_k);
    cudaGetSymbolAddress((void**)&p_pe, g_pe);

    proj_gemm_kernel<<<dim3(256, 3), 256>>>(lm_pruned, W_lm, b_lm, p_lm, 180);
    proj_gemm_kernel<<<dim3(256, 3), 256>>>(am_pruned, W_am, b_am, p_k, 160);
    pe_proj_kernel<<<80, 256>>>(pos_emb, W_pos, p_pe);

    const int smem_bytes = (32 * 512 + 32 * 32) * 4 + 544 * 16 + 32 * 16 + 512; // 79360
    cudaFuncSetAttribute(attn_kernel, cudaFuncAttributeMaxDynamicSharedMemorySize, smem_bytes);
    attn_kernel<<<dim3(16, 64, 5), 256, smem_bytes>>>(p_lm, p_k, p_pe, kpm, out);
}